// round 1
// baseline (speedup 1.0000x reference)
#include <cuda_runtime.h>
#include <cuda_bf16.h>
#include <math.h>

#define N_USERS 20000
#define N_ENT   80000
#define N_NODES (N_USERS + N_ENT)
#define D       64
#define N_REL   33
#define E_MAX   1250000
#define EPS_ATT 1e-9f
#define EPS_NORM 1e-12f

// Scratch (allocation-free rule: __device__ globals)
__device__ __align__(16) float g_ego [(size_t)N_NODES * D];
__device__ __align__(16) float g_sum [(size_t)N_NODES * D];
__device__ __align__(16) float g_aggr[(size_t)N_NODES * D];
__device__ __align__(16) float g_ex  [E_MAX];
__device__ float g_denom[N_NODES];

// ---------------------------------------------------------------------------
// Init: ego = concat(user, entity); sum = ego; aggr = 0; denom = 0
// ---------------------------------------------------------------------------
__global__ void k_init(const float* __restrict__ ue, const float* __restrict__ ee) {
    size_t i = (size_t)blockIdx.x * blockDim.x + threadIdx.x;
    const size_t NU = (size_t)N_USERS * D;
    const size_t NT = (size_t)N_NODES * D;
    if (i < NT) {
        float v = (i < NU) ? ue[i] : ee[i - NU];
        g_ego[i] = v;
        g_sum[i] = v;
        g_aggr[i] = 0.f;
        if (i < N_NODES) g_denom[i] = 0.f;
    }
}

// ---------------------------------------------------------------------------
// Edge pass 1: warp per edge. ex[e] = exp(lrelu(sum_d h*t*r)); denom[src] += ex
// (segment-max subtraction dropped: exp(l)/ (sum exp(l)+eps) differs from the
//  max-stabilized form by ~eps/denom ~ 1e-10 relative — far below tolerance)
// ---------------------------------------------------------------------------
__global__ void k_edge_ex(const float* __restrict__ rel_emb,
                          const int* __restrict__ src,
                          const int* __restrict__ dst,
                          const int* __restrict__ rel,
                          int nE) {
    int idx  = blockIdx.x * blockDim.x + threadIdx.x;
    int e    = idx >> 5;
    int lane = idx & 31;
    if (e >= nE) return;
    int s = __ldg(&src[e]);
    int d = __ldg(&dst[e]);
    int r = __ldg(&rel[e]);

    float2 h  = *(const float2*)(g_ego + (size_t)s * D + lane * 2);
    float2 t  = *(const float2*)(g_ego + (size_t)d * D + lane * 2);
    float2 re = *(const float2*)(rel_emb + (size_t)r * D + lane * 2);

    float p = h.x * t.x * re.x + h.y * t.y * re.y;
    #pragma unroll
    for (int o = 16; o; o >>= 1) p += __shfl_xor_sync(0xffffffffu, p, o);

    if (lane == 0) {
        float lg = p > 0.f ? p : 0.01f * p;
        float ex = __expf(lg);
        g_ex[e] = ex;
        atomicAdd(&g_denom[s], ex);
    }
}

// ---------------------------------------------------------------------------
// Edge pass 2: att = ex/(denom[src]+eps); aggr[src] += t * att
// ---------------------------------------------------------------------------
__global__ void k_edge_scatter(const int* __restrict__ src,
                               const int* __restrict__ dst,
                               int nE) {
    int idx  = blockIdx.x * blockDim.x + threadIdx.x;
    int e    = idx >> 5;
    int lane = idx & 31;
    if (e >= nE) return;
    int s = __ldg(&src[e]);
    int d = __ldg(&dst[e]);

    float att = g_ex[e] / (g_denom[s] + EPS_ATT);
    float2 t = *(const float2*)(g_ego + (size_t)d * D + lane * 2);

    float* addr = g_aggr + (size_t)s * D + lane * 2;
    atomicAdd(addr,     t.x * att);
    atomicAdd(addr + 1, t.y * att);
}

// ---------------------------------------------------------------------------
// Node update: new = lrelu((ego+aggr)@W1 + (ego*aggr)@W2); normalize;
// sum += new; ego = new; reset aggr/denom for next layer.
// 4 nodes per 256-thread block; W1,W2 staged in shared.
// ---------------------------------------------------------------------------
#define NPB 4
__global__ void k_node_update(const float* __restrict__ W1,
                              const float* __restrict__ W2) {
    __shared__ float W1s[D * D];
    __shared__ float W2s[D * D];
    __shared__ float xs[NPB][D];
    __shared__ float ys[NPB][D];
    __shared__ float ssum[NPB * 2];

    int tid = threadIdx.x;
    #pragma unroll
    for (int i = tid; i < D * D; i += 256) {
        W1s[i] = W1[i];
        W2s[i] = W2[i];
    }

    int ln = tid >> 6;     // local node 0..3
    int j  = tid & 63;     // output column
    int n  = blockIdx.x * NPB + ln;
    bool valid = (n < N_NODES);

    float eg = 0.f, ag = 0.f;
    if (valid) {
        eg = g_ego [(size_t)n * D + j];
        ag = g_aggr[(size_t)n * D + j];
    }
    xs[ln][j] = eg + ag;
    ys[ln][j] = eg * ag;
    __syncthreads();

    float acc = 0.f;
    #pragma unroll
    for (int k = 0; k < D; k++) {
        acc = fmaf(xs[ln][k], W1s[k * D + j], acc);
        acc = fmaf(ys[ln][k], W2s[k * D + j], acc);
    }
    float v = acc > 0.f ? acc : 0.01f * acc;

    // L2 norm over 64 values (2 warps per node)
    float sq = v * v;
    #pragma unroll
    for (int o = 16; o; o >>= 1) sq += __shfl_xor_sync(0xffffffffu, sq, o);
    int warp = tid >> 5;
    if ((tid & 31) == 0) ssum[warp] = sq;
    __syncthreads();
    float tot = ssum[ln * 2] + ssum[ln * 2 + 1];
    float inv = 1.f / fmaxf(sqrtf(tot), EPS_NORM);
    v *= inv;

    if (valid) {
        size_t o = (size_t)n * D + j;
        g_ego[o]  = v;
        g_sum[o] += v;
        g_aggr[o] = 0.f;          // reset for next layer
        if (j == 0) g_denom[n] = 0.f;
    }
}

// ---------------------------------------------------------------------------
// Final: out = [ item(final[NU:]) | user(final[:NU]) ], final = sum/3
// ---------------------------------------------------------------------------
__global__ void k_final(float* __restrict__ out) {
    size_t i = (size_t)blockIdx.x * blockDim.x + threadIdx.x;
    const size_t NU = (size_t)N_USERS * D;
    const size_t NT = (size_t)N_NODES * D;
    const size_t NE = (size_t)N_ENT * D;
    if (i < NT) {
        float v = g_sum[i] * (1.f / 3.f);
        if (i < NU) out[NE + i] = v;        // user part goes after items
        else        out[i - NU] = v;        // item part first
    }
}

// ---------------------------------------------------------------------------
extern "C" void kernel_launch(void* const* d_in, const int* in_sizes, int n_in,
                              void* d_out, int out_size) {
    const float* user_emb = (const float*)d_in[0];
    const float* ent_emb  = (const float*)d_in[1];
    const float* rel_emb  = (const float*)d_in[2];
    const float* W1       = (const float*)d_in[3];
    const float* W2       = (const float*)d_in[4];
    const int*   src      = (const int*)d_in[5];
    const int*   dst      = (const int*)d_in[6];
    const int*   rel      = (const int*)d_in[7];
    float* out = (float*)d_out;

    int nE = in_sizes[5];
    if (nE > E_MAX) nE = E_MAX;

    const int nodeElems = N_NODES * D;
    int initBlocks  = (nodeElems + 255) / 256;
    long long eThreads = (long long)nE * 32;
    int eBlocks = (int)((eThreads + 255) / 256);
    int nBlocks = (N_NODES + NPB - 1) / NPB;

    k_init<<<initBlocks, 256>>>(user_emb, ent_emb);

    for (int layer = 0; layer < 2; layer++) {
        k_edge_ex<<<eBlocks, 256>>>(rel_emb, src, dst, rel, nE);
        k_edge_scatter<<<eBlocks, 256>>>(src, dst, nE);
        k_node_update<<<nBlocks, 256>>>(W1, W2);
    }

    k_final<<<initBlocks, 256>>>(out);
}

// round 2
// speedup vs baseline: 2.1521x; 2.1521x over previous
#include <cuda_runtime.h>
#include <math.h>

#define N_USERS 20000
#define N_ENT   80000
#define N_NODES (N_USERS + N_ENT)
#define D       64
#define E_MAX   1250000
#define EPS_ATT 1e-9f
#define EPS_NORM 1e-12f

#define SCAN_BLK 1024
#define N_SCAN_BLOCKS ((N_NODES + SCAN_BLK - 1) / SCAN_BLK)   // 98

// Scratch (__device__ globals; no allocation allowed)
__device__ __align__(16) float g_ego [(size_t)N_NODES * D];
__device__ __align__(16) float g_sum [(size_t)N_NODES * D];
__device__ __align__(16) float g_aggr[(size_t)N_NODES * D];
__device__ int  g_hist    [N_NODES];
__device__ int  g_segstart[N_NODES + 1];
__device__ int  g_cursor  [N_NODES];
__device__ int2 g_dr      [E_MAX];          // sorted (dst, rel) per edge
__device__ int  g_bsum    [N_SCAN_BLOCKS];
__device__ int  g_boff    [N_SCAN_BLOCKS];

// ---------------------------------------------------------------------------
// Init: ego = concat(user, entity); sum = ego; zero histogram
// ---------------------------------------------------------------------------
__global__ void k_init(const float* __restrict__ ue, const float* __restrict__ ee) {
    size_t i = (size_t)blockIdx.x * blockDim.x + threadIdx.x;
    const size_t NU = (size_t)N_USERS * D;
    const size_t NT = (size_t)N_NODES * D;
    if (i < NT) {
        float v = (i < NU) ? ue[i] : ee[i - NU];
        g_ego[i] = v;
        g_sum[i] = v;
        if (i < N_NODES) g_hist[i] = 0;
    }
}

// ---------------------------------------------------------------------------
// Counting sort by src: histogram -> scan -> permute (dst, rel)
// ---------------------------------------------------------------------------
__global__ void k_hist(const int* __restrict__ src, int nE) {
    int e = blockIdx.x * blockDim.x + threadIdx.x;
    if (e < nE) atomicAdd(&g_hist[src[e]], 1);
}

__global__ void k_scan_a() {
    __shared__ int s[SCAN_BLK];
    int t = threadIdx.x;
    int i = blockIdx.x * SCAN_BLK + t;
    int v = (i < N_NODES) ? g_hist[i] : 0;
    s[t] = v;
    __syncthreads();
    #pragma unroll
    for (int o = 1; o < SCAN_BLK; o <<= 1) {
        int add = (t >= o) ? s[t - o] : 0;
        __syncthreads();
        s[t] += add;
        __syncthreads();
    }
    if (i < N_NODES) g_segstart[i] = s[t] - v;            // exclusive within block
    if (t == SCAN_BLK - 1) g_bsum[blockIdx.x] = s[t];     // block total
}

__global__ void k_scan_b() {
    if (threadIdx.x == 0) {
        int run = 0;
        for (int b = 0; b < N_SCAN_BLOCKS; b++) {
            g_boff[b] = run;
            run += g_bsum[b];
        }
    }
}

__global__ void k_scan_c(int nE) {
    int i = blockIdx.x * blockDim.x + threadIdx.x;
    if (i < N_NODES) {
        int v = g_segstart[i] + g_boff[i / SCAN_BLK];
        g_segstart[i] = v;
        g_cursor[i]   = v;
    }
    if (i == 0) g_segstart[N_NODES] = nE;
}

__global__ void k_permute(const int* __restrict__ src, const int* __restrict__ dst,
                          const int* __restrict__ rel, int nE) {
    int e = blockIdx.x * blockDim.x + threadIdx.x;
    if (e < nE) {
        int pos = atomicAdd(&g_cursor[src[e]], 1);
        g_dr[pos] = make_int2(dst[e], rel[e]);
    }
}

// ---------------------------------------------------------------------------
// Fused attention layer: one warp per source node.
//   aggr[n] = (sum_e t_e * ex_e) / (sum_e ex_e + eps),  ex_e = exp(lrelu(h.t.r))
// Normalization factors out -> single edge pass, no atomics, no g_ex.
// (segment-max stabilization dropped: logits ~ +-0.1, error ~1e-10 rel)
// ---------------------------------------------------------------------------
__global__ void k_edge(const float* __restrict__ rel_emb) {
    int gw   = (blockIdx.x * blockDim.x + threadIdx.x) >> 5;
    int lane = threadIdx.x & 31;
    if (gw >= N_NODES) return;

    int beg = g_segstart[gw];
    int end = g_segstart[gw + 1];

    float2 h = *(const float2*)(g_ego + (size_t)gw * D + lane * 2);
    float denom = 0.f;
    float accx = 0.f, accy = 0.f;

    for (int e = beg; e < end; e++) {
        int2 dr = g_dr[e];
        float2 t  = *(const float2*)(g_ego   + (size_t)dr.x * D + lane * 2);
        float2 re = *(const float2*)(rel_emb + (size_t)dr.y * D + lane * 2);
        float p = h.x * t.x * re.x;
        p = fmaf(h.y * t.y, re.y, p);
        #pragma unroll
        for (int o = 16; o; o >>= 1) p += __shfl_xor_sync(0xffffffffu, p, o);
        float lg = p > 0.f ? p : 0.01f * p;
        float ex = __expf(lg);
        denom += ex;
        accx = fmaf(t.x, ex, accx);
        accy = fmaf(t.y, ex, accy);
    }

    float inv = 1.f / (denom + EPS_ATT);
    *(float2*)(g_aggr + (size_t)gw * D + lane * 2) = make_float2(accx * inv, accy * inv);
}

// ---------------------------------------------------------------------------
// Node update: new = lrelu((ego+aggr)@W1 + (ego*aggr)@W2); L2-normalize;
// sum += new; ego = new.  16 nodes/block, 16 threads/node x 4 cols (float4 W).
// ---------------------------------------------------------------------------
#define NPB 16
__global__ void k_node(const float* __restrict__ W1, const float* __restrict__ W2) {
    __shared__ __align__(16) float W1s[D * D];
    __shared__ __align__(16) float W2s[D * D];
    __shared__ float xs[NPB][D + 1];
    __shared__ float ys[NPB][D + 1];

    int tid = threadIdx.x;
    #pragma unroll
    for (int i = tid; i < D * D; i += 256) {
        W1s[i] = W1[i];
        W2s[i] = W2[i];
    }

    int base = blockIdx.x * NPB;
    #pragma unroll
    for (int i = 0; i < 4; i++) {
        int idx = tid + i * 256;          // 0..1023 over [16][64]
        int ln = idx >> 6, c = idx & 63;
        int n = base + ln;
        float eg = 0.f, ag = 0.f;
        if (n < N_NODES) {
            eg = g_ego [(size_t)n * D + c];
            ag = g_aggr[(size_t)n * D + c];
        }
        xs[ln][c] = eg + ag;
        ys[ln][c] = eg * ag;
    }
    __syncthreads();

    int ln = tid >> 4;                    // node within block (0..15)
    int c0 = (tid & 15) * 4;              // 4 output columns per thread
    int n  = base + ln;

    float a0 = 0.f, a1 = 0.f, a2 = 0.f, a3 = 0.f;
    #pragma unroll
    for (int k = 0; k < D; k++) {
        float xk = xs[ln][k];
        float yk = ys[ln][k];
        float4 w1 = *(const float4*)&W1s[k * D + c0];
        float4 w2 = *(const float4*)&W2s[k * D + c0];
        a0 = fmaf(xk, w1.x, a0); a1 = fmaf(xk, w1.y, a1);
        a2 = fmaf(xk, w1.z, a2); a3 = fmaf(xk, w1.w, a3);
        a0 = fmaf(yk, w2.x, a0); a1 = fmaf(yk, w2.y, a1);
        a2 = fmaf(yk, w2.z, a2); a3 = fmaf(yk, w2.w, a3);
    }
    a0 = a0 > 0.f ? a0 : 0.01f * a0;
    a1 = a1 > 0.f ? a1 : 0.01f * a1;
    a2 = a2 > 0.f ? a2 : 0.01f * a2;
    a3 = a3 > 0.f ? a3 : 0.01f * a3;

    float sq = a0 * a0 + a1 * a1 + a2 * a2 + a3 * a3;
    #pragma unroll
    for (int o = 8; o; o >>= 1) sq += __shfl_xor_sync(0xffffffffu, sq, o);
    float inv = 1.f / fmaxf(sqrtf(sq), EPS_NORM);
    a0 *= inv; a1 *= inv; a2 *= inv; a3 *= inv;

    if (n < N_NODES) {
        size_t o = (size_t)n * D + c0;
        float4 s = *(const float4*)&g_sum[o];
        *(float4*)&g_ego[o] = make_float4(a0, a1, a2, a3);
        *(float4*)&g_sum[o] = make_float4(s.x + a0, s.y + a1, s.z + a2, s.w + a3);
    }
}

// ---------------------------------------------------------------------------
// Final: out = [ item(final[NU:]) | user(final[:NU]) ], final = sum / 3
// ---------------------------------------------------------------------------
__global__ void k_final(float* __restrict__ out) {
    size_t i = (size_t)blockIdx.x * blockDim.x + threadIdx.x;
    const size_t NU = (size_t)N_USERS * D;
    const size_t NT = (size_t)N_NODES * D;
    const size_t NE = (size_t)N_ENT * D;
    if (i < NT) {
        float v = g_sum[i] * (1.f / 3.f);
        if (i < NU) out[NE + i] = v;        // user part after items
        else        out[i - NU] = v;        // items first
    }
}

// ---------------------------------------------------------------------------
extern "C" void kernel_launch(void* const* d_in, const int* in_sizes, int n_in,
                              void* d_out, int out_size) {
    const float* user_emb = (const float*)d_in[0];
    const float* ent_emb  = (const float*)d_in[1];
    const float* rel_emb  = (const float*)d_in[2];
    const float* W1       = (const float*)d_in[3];
    const float* W2       = (const float*)d_in[4];
    const int*   src      = (const int*)d_in[5];
    const int*   dst      = (const int*)d_in[6];
    const int*   rel      = (const int*)d_in[7];
    float* out = (float*)d_out;

    int nE = in_sizes[5];
    if (nE > E_MAX) nE = E_MAX;

    const int nodeElems = N_NODES * D;
    int initBlocks = (nodeElems + 255) / 256;
    int eBlocks    = (nE + 255) / 256;
    int segBlocks  = (N_NODES + 255) / 256;
    int edgeBlocks = (N_NODES * 32 + 255) / 256;   // warp per node
    int nodeBlocks = (N_NODES + NPB - 1) / NPB;

    k_init<<<initBlocks, 256>>>(user_emb, ent_emb);
    k_hist<<<eBlocks, 256>>>(src, nE);
    k_scan_a<<<N_SCAN_BLOCKS, SCAN_BLK>>>();
    k_scan_b<<<1, 32>>>();
    k_scan_c<<<segBlocks, 256>>>(nE);
    k_permute<<<eBlocks, 256>>>(src, dst, rel, nE);

    for (int layer = 0; layer < 2; layer++) {
        k_edge<<<edgeBlocks, 256>>>(rel_emb);
        k_node<<<nodeBlocks, 256>>>(W1, W2);
    }

    k_final<<<initBlocks, 256>>>(out);
}

// round 3
// speedup vs baseline: 2.2851x; 1.0618x over previous
#include <cuda_runtime.h>
#include <math.h>

#define N_USERS 20000
#define N_ENT   80000
#define N_NODES (N_USERS + N_ENT)
#define D       64
#define E_MAX   1250000
#define EPS_ATT 1e-9f
#define EPS_NORM 1e-12f

#define SCAN_BLK 1024
#define N_SCAN_BLOCKS ((N_NODES + SCAN_BLK - 1) / SCAN_BLK)   // 98

// Scratch (__device__ globals; no allocation allowed)
__device__ __align__(16) float g_ego [(size_t)N_NODES * D];
__device__ __align__(16) float g_sum [(size_t)N_NODES * D];
__device__ __align__(16) float g_aggr[(size_t)N_NODES * D];
__device__ int  g_hist    [N_NODES];     // zero-init at load; re-zeroed by k_scan_a each launch
__device__ int  g_segstart[N_NODES + 1];
__device__ int  g_cursor  [N_NODES];
__device__ int2 g_dr      [E_MAX];       // sorted (dst, rel) per edge
__device__ int  g_bsum    [N_SCAN_BLOCKS];
__device__ int  g_boff    [N_SCAN_BLOCKS];

// ---------------------------------------------------------------------------
// Init (fused with histogram): ego = concat(user, entity); sum = ego;
// hist[src[e]]++ (g_hist is guaranteed zero: module zero-init on first call,
// re-zeroed inside k_scan_a on every launch -> graph replay stays idempotent)
// ---------------------------------------------------------------------------
__global__ void k_init(const float* __restrict__ ue, const float* __restrict__ ee,
                       const int* __restrict__ src, int nE) {
    size_t i = (size_t)blockIdx.x * blockDim.x + threadIdx.x;
    const size_t NU = (size_t)N_USERS * D;
    const size_t NT = (size_t)N_NODES * D;
    if (i < NT) {
        float v = (i < NU) ? ue[i] : ee[i - NU];
        g_ego[i] = v;
        g_sum[i] = v;
    }
    if (i < (size_t)nE) atomicAdd(&g_hist[src[i]], 1);
}

// ---------------------------------------------------------------------------
// Two-level exclusive scan of hist -> segstart
// ---------------------------------------------------------------------------
__global__ void k_scan_a() {
    __shared__ int s[SCAN_BLK];
    int t = threadIdx.x;
    int i = blockIdx.x * SCAN_BLK + t;
    int v = (i < N_NODES) ? g_hist[i] : 0;
    if (i < N_NODES) g_hist[i] = 0;                       // re-zero for next launch
    s[t] = v;
    __syncthreads();
    #pragma unroll
    for (int o = 1; o < SCAN_BLK; o <<= 1) {
        int add = (t >= o) ? s[t - o] : 0;
        __syncthreads();
        s[t] += add;
        __syncthreads();
    }
    if (i < N_NODES) g_segstart[i] = s[t] - v;            // exclusive within block
    if (t == SCAN_BLK - 1) g_bsum[blockIdx.x] = s[t];     // block total
}

__global__ void k_scan_b() {                              // parallel scan of 98 sums
    __shared__ int s[128];
    int t = threadIdx.x;
    int v = (t < N_SCAN_BLOCKS) ? g_bsum[t] : 0;
    s[t] = v;
    __syncthreads();
    #pragma unroll
    for (int o = 1; o < 128; o <<= 1) {
        int add = (t >= o) ? s[t - o] : 0;
        __syncthreads();
        s[t] += add;
        __syncthreads();
    }
    if (t < N_SCAN_BLOCKS) g_boff[t] = s[t] - v;          // exclusive
}

__global__ void k_scan_c(int nE) {
    int i = blockIdx.x * blockDim.x + threadIdx.x;
    if (i < N_NODES) {
        int v = g_segstart[i] + g_boff[i / SCAN_BLK];
        g_segstart[i] = v;
        g_cursor[i]   = v;
    }
    if (i == 0) g_segstart[N_NODES] = nE;
}

__global__ void k_permute(const int* __restrict__ src, const int* __restrict__ dst,
                          const int* __restrict__ rel, int nE) {
    int e = blockIdx.x * blockDim.x + threadIdx.x;
    if (e < nE) {
        int pos = atomicAdd(&g_cursor[src[e]], 1);
        g_dr[pos] = make_int2(dst[e], rel[e]);
    }
}

// ---------------------------------------------------------------------------
// Fused attention layer: one warp per source node, edge loop unrolled x2 with
// independent reduction chains (doubles gather MLP, overlaps SHFL latency).
//   aggr[n] = (sum_e t_e * ex_e) / (sum_e ex_e + eps),  ex_e = exp(lrelu(h.t.r))
// ---------------------------------------------------------------------------
__global__ void k_edge(const float* __restrict__ rel_emb) {
    int gw   = (blockIdx.x * blockDim.x + threadIdx.x) >> 5;
    int lane = threadIdx.x & 31;
    if (gw >= N_NODES) return;

    int beg = g_segstart[gw];
    int end = g_segstart[gw + 1];

    float2 h = *(const float2*)(g_ego + (size_t)gw * D + lane * 2);
    float denom = 0.f;
    float accx = 0.f, accy = 0.f;

    int e = beg;
    for (; e + 2 <= end; e += 2) {
        int2 d0 = g_dr[e];
        int2 d1 = g_dr[e + 1];
        float2 t0 = *(const float2*)(g_ego   + (size_t)d0.x * D + lane * 2);
        float2 t1 = *(const float2*)(g_ego   + (size_t)d1.x * D + lane * 2);
        float2 r0 = *(const float2*)(rel_emb + (size_t)d0.y * D + lane * 2);
        float2 r1 = *(const float2*)(rel_emb + (size_t)d1.y * D + lane * 2);

        float p0 = h.x * t0.x * r0.x;  p0 = fmaf(h.y * t0.y, r0.y, p0);
        float p1 = h.x * t1.x * r1.x;  p1 = fmaf(h.y * t1.y, r1.y, p1);
        #pragma unroll
        for (int o = 16; o; o >>= 1) {
            p0 += __shfl_xor_sync(0xffffffffu, p0, o);
            p1 += __shfl_xor_sync(0xffffffffu, p1, o);
        }
        float l0 = p0 > 0.f ? p0 : 0.01f * p0;
        float l1 = p1 > 0.f ? p1 : 0.01f * p1;
        float e0 = __expf(l0);
        float e1 = __expf(l1);
        denom += e0 + e1;
        accx = fmaf(t0.x, e0, accx);  accx = fmaf(t1.x, e1, accx);
        accy = fmaf(t0.y, e0, accy);  accy = fmaf(t1.y, e1, accy);
    }
    if (e < end) {
        int2 d0 = g_dr[e];
        float2 t0 = *(const float2*)(g_ego   + (size_t)d0.x * D + lane * 2);
        float2 r0 = *(const float2*)(rel_emb + (size_t)d0.y * D + lane * 2);
        float p0 = h.x * t0.x * r0.x;  p0 = fmaf(h.y * t0.y, r0.y, p0);
        #pragma unroll
        for (int o = 16; o; o >>= 1) p0 += __shfl_xor_sync(0xffffffffu, p0, o);
        float l0 = p0 > 0.f ? p0 : 0.01f * p0;
        float e0 = __expf(l0);
        denom += e0;
        accx = fmaf(t0.x, e0, accx);
        accy = fmaf(t0.y, e0, accy);
    }

    float inv = 1.f / (denom + EPS_ATT);
    *(float2*)(g_aggr + (size_t)gw * D + lane * 2) = make_float2(accx * inv, accy * inv);
}

// ---------------------------------------------------------------------------
// Node update: new = lrelu((ego+aggr)@W1 + (ego*aggr)@W2); L2-normalize.
// Non-final: ego = new, sum += new.
// Final:     out  = (sum + new) / 3, permuted [items | users]; g_ego/g_sum
//            untouched (dead after this).
// 16 nodes/block, 16 threads/node x 4 cols (float4 W from shared).
// ---------------------------------------------------------------------------
#define NPB 16
template <bool FINAL>
__global__ void k_node(const float* __restrict__ W1, const float* __restrict__ W2,
                       float* __restrict__ out) {
    __shared__ __align__(16) float W1s[D * D];
    __shared__ __align__(16) float W2s[D * D];
    __shared__ float xs[NPB][D + 1];
    __shared__ float ys[NPB][D + 1];

    int tid = threadIdx.x;
    #pragma unroll
    for (int i = tid; i < D * D; i += 256) {
        W1s[i] = W1[i];
        W2s[i] = W2[i];
    }

    int base = blockIdx.x * NPB;
    #pragma unroll
    for (int i = 0; i < 4; i++) {
        int idx = tid + i * 256;          // 0..1023 over [16][64]
        int ln = idx >> 6, c = idx & 63;
        int n = base + ln;
        float eg = 0.f, ag = 0.f;
        if (n < N_NODES) {
            eg = g_ego [(size_t)n * D + c];
            ag = g_aggr[(size_t)n * D + c];
        }
        xs[ln][c] = eg + ag;
        ys[ln][c] = eg * ag;
    }
    __syncthreads();

    int ln = tid >> 4;                    // node within block (0..15)
    int c0 = (tid & 15) * 4;              // 4 output columns per thread
    int n  = base + ln;

    float a0 = 0.f, a1 = 0.f, a2 = 0.f, a3 = 0.f;
    #pragma unroll
    for (int k = 0; k < D; k++) {
        float xk = xs[ln][k];
        float yk = ys[ln][k];
        float4 w1 = *(const float4*)&W1s[k * D + c0];
        float4 w2 = *(const float4*)&W2s[k * D + c0];
        a0 = fmaf(xk, w1.x, a0); a1 = fmaf(xk, w1.y, a1);
        a2 = fmaf(xk, w1.z, a2); a3 = fmaf(xk, w1.w, a3);
        a0 = fmaf(yk, w2.x, a0); a1 = fmaf(yk, w2.y, a1);
        a2 = fmaf(yk, w2.z, a2); a3 = fmaf(yk, w2.w, a3);
    }
    a0 = a0 > 0.f ? a0 : 0.01f * a0;
    a1 = a1 > 0.f ? a1 : 0.01f * a1;
    a2 = a2 > 0.f ? a2 : 0.01f * a2;
    a3 = a3 > 0.f ? a3 : 0.01f * a3;

    float sq = a0 * a0 + a1 * a1 + a2 * a2 + a3 * a3;
    #pragma unroll
    for (int o = 8; o; o >>= 1) sq += __shfl_xor_sync(0xffffffffu, sq, o);
    float inv = 1.f / fmaxf(sqrtf(sq), EPS_NORM);
    a0 *= inv; a1 *= inv; a2 *= inv; a3 *= inv;

    if (n < N_NODES) {
        size_t o = (size_t)n * D + c0;
        float4 s = *(const float4*)&g_sum[o];
        if (FINAL) {
            // out = [item rows (n >= N_USERS) | user rows (n < N_USERS)]
            size_t orow = (n >= N_USERS) ? (size_t)(n - N_USERS)
                                         : (size_t)(N_ENT + n);
            *(float4*)&out[orow * D + c0] = make_float4(
                (s.x + a0) * (1.f / 3.f), (s.y + a1) * (1.f / 3.f),
                (s.z + a2) * (1.f / 3.f), (s.w + a3) * (1.f / 3.f));
        } else {
            *(float4*)&g_ego[o] = make_float4(a0, a1, a2, a3);
            *(float4*)&g_sum[o] = make_float4(s.x + a0, s.y + a1, s.z + a2, s.w + a3);
        }
    }
}

// ---------------------------------------------------------------------------
extern "C" void kernel_launch(void* const* d_in, const int* in_sizes, int n_in,
                              void* d_out, int out_size) {
    const float* user_emb = (const float*)d_in[0];
    const float* ent_emb  = (const float*)d_in[1];
    const float* rel_emb  = (const float*)d_in[2];
    const float* W1       = (const float*)d_in[3];
    const float* W2       = (const float*)d_in[4];
    const int*   src      = (const int*)d_in[5];
    const int*   dst      = (const int*)d_in[6];
    const int*   rel      = (const int*)d_in[7];
    float* out = (float*)d_out;

    int nE = in_sizes[5];
    if (nE > E_MAX) nE = E_MAX;

    const int nodeElems = N_NODES * D;
    int initBlocks = (nodeElems + 255) / 256;       // covers nE too (6.4M > 1.25M)
    int eBlocks    = (nE + 255) / 256;
    int segBlocks  = (N_NODES + 255) / 256;
    int edgeBlocks = (N_NODES * 32 + 255) / 256;    // warp per node
    int nodeBlocks = (N_NODES + NPB - 1) / NPB;

    k_init<<<initBlocks, 256>>>(user_emb, ent_emb, src, nE);
    k_scan_a<<<N_SCAN_BLOCKS, SCAN_BLK>>>();
    k_scan_b<<<1, 128>>>();
    k_scan_c<<<segBlocks, 256>>>(nE);
    k_permute<<<eBlocks, 256>>>(src, dst, rel, nE);

    k_edge<<<edgeBlocks, 256>>>(rel_emb);
    k_node<false><<<nodeBlocks, 256>>>(W1, W2, out);
    k_edge<<<edgeBlocks, 256>>>(rel_emb);
    k_node<true><<<nodeBlocks, 256>>>(W1, W2, out);
}